// round 2
// baseline (speedup 1.0000x reference)
#include <cuda_runtime.h>
#include <cuda_bf16.h>

// Problem constants
#define T_DIM 8
#define C_DIM 3
#define HW    65536   // 256*256
#define NPIX  262144  // B(4) * HW

// Folded constants: per head n (25 floats):
//   [0..8]   MT[j][i]  : r_j = u_j + sum_i MT[j][i] * z7_i
//   [9..11]  u[j]
//   [12..14] g[i]      : s = c + sum_i g[i]*z7_i
//   [15]     c
//   [16..24] P[o][i]   : out_o += sum_i P[o][i] * zbar_i
// [100..102] p_total[o] (all biases folded, includes b_o)
__device__ float g_const[103];

__global__ void setup_kernel(const float* __restrict__ W_in, const float* __restrict__ b_in,
                             const float* __restrict__ W_q,  const float* __restrict__ b_q,
                             const float* __restrict__ W_k,  const float* __restrict__ b_k,
                             const float* __restrict__ W_v,  const float* __restrict__ b_v,
                             const float* __restrict__ W_o,  const float* __restrict__ b_o) {
    // A = W_q @ W_in (32x3), aQ = W_q@b_in + b_q (32); same for k (Bm,bK) and v (Cm,cV)
    __shared__ float A[32][3], Bm[32][3], Cm[32][3];
    __shared__ float aQ[32], bK[32], cV[32];
    int tid = threadIdx.x;  // 128 threads

    for (int task = tid; task < 384; task += 128) {
        int m = task >> 7;          // 0:q 1:k 2:v
        int r = task & 127;         // 0..95 matrix entry, 96..127 bias entry
        const float* Wm = (m == 0) ? W_q : (m == 1) ? W_k : W_v;
        const float* bm = (m == 0) ? b_q : (m == 1) ? b_k : b_v;
        if (r < 96) {
            int o = r / 3, i = r - 3 * o;
            float s = 0.f;
            #pragma unroll
            for (int j = 0; j < 32; j++) s += Wm[o * 32 + j] * W_in[j * 3 + i];
            if (m == 0) A[o][i] = s; else if (m == 1) Bm[o][i] = s; else Cm[o][i] = s;
        } else {
            int o = r - 96;
            float s = bm[o];
            #pragma unroll
            for (int j = 0; j < 32; j++) s += Wm[o * 32 + j] * b_in[j];
            if (m == 0) aQ[o] = s; else if (m == 1) bK[o] = s; else cV[o] = s;
        }
    }
    __syncthreads();

    const float scale = 0.3535533905932738f;  // 1/sqrt(DK=8)
    if (tid < 103) {
        float s = 0.f;
        if (tid >= 100) {
            int o = tid - 100;
            s = b_o[o];
            #pragma unroll
            for (int r = 0; r < 32; r++) s += W_o[o * 32 + r] * cV[r];
        } else {
            int n = tid / 25, k = tid - 25 * n;
            int base = n * 8;
            if (k < 9) {                     // MT[j][i] = scale * sum_d A[d][i]*B[d][j]
                int j = k / 3, i = k - 3 * j;
                #pragma unroll
                for (int d = 0; d < 8; d++) s += A[base + d][i] * Bm[base + d][j];
                s *= scale;
            } else if (k < 12) {             // u[j] = scale * sum_d aQ[d]*B[d][j]
                int j = k - 9;
                #pragma unroll
                for (int d = 0; d < 8; d++) s += aQ[base + d] * Bm[base + d][j];
                s *= scale;
            } else if (k < 15) {             // g[i] = scale * sum_d A[d][i]*bK[d]
                int i = k - 12;
                #pragma unroll
                for (int d = 0; d < 8; d++) s += A[base + d][i] * bK[base + d];
                s *= scale;
            } else if (k == 15) {            // c = scale * sum_d aQ[d]*bK[d]
                #pragma unroll
                for (int d = 0; d < 8; d++) s += aQ[base + d] * bK[base + d];
                s *= scale;
            } else {                         // P[o][i] = sum_d W_o[o][base+d]*C[base+d][i]
                int kk = k - 16;
                int o = kk / 3, i = kk - 3 * o;
                #pragma unroll
                for (int d = 0; d < 8; d++) s += W_o[o * 32 + base + d] * Cm[base + d][i];
            }
        }
        g_const[tid] = s;
    }
}

__global__ void __launch_bounds__(256)
attn_kernel(const float* __restrict__ z, float* __restrict__ out) {
    __shared__ float cst[103];
    int tid = threadIdx.x;
    if (tid < 103) cst[tid] = g_const[tid];
    __syncthreads();

    int pix = blockIdx.x * 256 + tid;
    if (pix >= NPIX) return;
    int b  = pix >> 16;          // HW = 2^16
    int hw = pix & (HW - 1);

    const float* zp = z + (size_t)b * (T_DIM * C_DIM * HW) + hw;
    float zv[T_DIM][C_DIM];
    #pragma unroll
    for (int t = 0; t < T_DIM; t++)
        #pragma unroll
        for (int c = 0; c < C_DIM; c++)
            zv[t][c] = zp[(t * C_DIM + c) * HW];

    float z70 = zv[7][0], z71 = zv[7][1], z72 = zv[7][2];
    float o0 = cst[100], o1 = cst[101], o2 = cst[102];

    #pragma unroll
    for (int n = 0; n < 4; n++) {
        const float* cs = cst + n * 25;
        float r0 = cs[9]  + cs[0] * z70 + cs[1] * z71 + cs[2] * z72;
        float r1 = cs[10] + cs[3] * z70 + cs[4] * z71 + cs[5] * z72;
        float r2 = cs[11] + cs[6] * z70 + cs[7] * z71 + cs[8] * z72;
        float s  = cs[15] + cs[12] * z70 + cs[13] * z71 + cs[14] * z72;

        float sc[T_DIM];
        float m = -1e30f;
        #pragma unroll
        for (int t = 0; t < T_DIM; t++) {
            sc[t] = s + r0 * zv[t][0] + r1 * zv[t][1] + r2 * zv[t][2];
            m = fmaxf(m, sc[t]);
        }
        float esum = 0.f, zb0 = 0.f, zb1 = 0.f, zb2 = 0.f;
        #pragma unroll
        for (int t = 0; t < T_DIM; t++) {
            float e = __expf(sc[t] - m);
            esum += e;
            zb0 += e * zv[t][0];
            zb1 += e * zv[t][1];
            zb2 += e * zv[t][2];
        }
        float inv = 1.0f / esum;
        zb0 *= inv; zb1 *= inv; zb2 *= inv;
        o0 += cs[16] * zb0 + cs[17] * zb1 + cs[18] * zb2;
        o1 += cs[19] * zb0 + cs[20] * zb1 + cs[21] * zb2;
        o2 += cs[22] * zb0 + cs[23] * zb1 + cs[24] * zb2;
    }

    float* op = out + (size_t)b * (3 * HW) + hw;
    op[0]      = o0;
    op[HW]     = o1;
    op[2 * HW] = o2;
}

extern "C" void kernel_launch(void* const* d_in, const int* in_sizes, int n_in,
                              void* d_out, int out_size) {
    const float* z    = (const float*)d_in[0];
    const float* W_in = (const float*)d_in[1];
    const float* b_in = (const float*)d_in[2];
    const float* W_q  = (const float*)d_in[3];
    const float* b_q  = (const float*)d_in[4];
    const float* W_k  = (const float*)d_in[5];
    const float* b_k  = (const float*)d_in[6];
    const float* W_v  = (const float*)d_in[7];
    const float* b_v  = (const float*)d_in[8];
    const float* W_o  = (const float*)d_in[9];
    const float* b_o  = (const float*)d_in[10];
    float* out = (float*)d_out;

    setup_kernel<<<1, 128>>>(W_in, b_in, W_q, b_q, W_k, b_k, W_v, b_v, W_o, b_o);
    attn_kernel<<<NPIX / 256, 256>>>(z, out);
}

// round 3
// speedup vs baseline: 1.0292x; 1.0292x over previous
#include <cuda_runtime.h>
#include <cuda_bf16.h>

// Problem constants
#define T_DIM 8
#define C_DIM 3
#define HW    65536   // 256*256
#define NPIX  262144  // B(4) * HW

// Folded constants (score-path entries pre-multiplied by log2(e) so we can use
// raw ex2.approx): per head n (25 floats):
//   [0..8]   MT[j][i]  : r_j = u_j + sum_i MT[j][i] * z7_i        (base-2 scaled)
//   [9..11]  u[j]                                                  (base-2 scaled)
//   [12..14] g[i]      : s = c + sum_i g[i]*z7_i                   (base-2 scaled)
//   [15]     c                                                     (base-2 scaled)
//   [16..24] P[o][i]   : out_o += sum_i P[o][i] * zbar_i
// [100..102] p_total[o]
__device__ float g_const[103];

// ---------------- packed f32x2 helpers (Blackwell) ----------------
typedef unsigned long long f32x2;

__device__ __forceinline__ f32x2 pack2(float lo, float hi) {
    f32x2 r; asm("mov.b64 %0, {%1, %2};" : "=l"(r) : "f"(lo), "f"(hi)); return r;
}
__device__ __forceinline__ void unpack2(f32x2 v, float& lo, float& hi) {
    asm("mov.b64 {%0, %1}, %2;" : "=f"(lo), "=f"(hi) : "l"(v));
}
__device__ __forceinline__ f32x2 fma2(f32x2 a, f32x2 b, f32x2 c) {
    f32x2 d; asm("fma.rn.f32x2 %0, %1, %2, %3;" : "=l"(d) : "l"(a), "l"(b), "l"(c)); return d;
}
__device__ __forceinline__ f32x2 add2(f32x2 a, f32x2 b) {
    f32x2 d; asm("add.rn.f32x2 %0, %1, %2;" : "=l"(d) : "l"(a), "l"(b)); return d;
}
__device__ __forceinline__ f32x2 mul2(f32x2 a, f32x2 b) {
    f32x2 d; asm("mul.rn.f32x2 %0, %1, %2;" : "=l"(d) : "l"(a), "l"(b)); return d;
}
__device__ __forceinline__ f32x2 ex2_2(f32x2 v) {
    float lo, hi; unpack2(v, lo, hi);
    float el, eh;
    asm("ex2.approx.ftz.f32 %0, %1;" : "=f"(el) : "f"(lo));
    asm("ex2.approx.ftz.f32 %0, %1;" : "=f"(eh) : "f"(hi));
    return pack2(el, eh);
}
__device__ __forceinline__ f32x2 rcp_2(f32x2 v) {
    float lo, hi; unpack2(v, lo, hi);
    float rl, rh;
    asm("rcp.approx.ftz.f32 %0, %1;" : "=f"(rl) : "f"(lo));
    asm("rcp.approx.ftz.f32 %0, %1;" : "=f"(rh) : "f"(hi));
    return pack2(rl, rh);
}

// ---------------- setup: fold all weights into 103 constants ----------------
__global__ void setup_kernel(const float* __restrict__ W_in, const float* __restrict__ b_in,
                             const float* __restrict__ W_q,  const float* __restrict__ b_q,
                             const float* __restrict__ W_k,  const float* __restrict__ b_k,
                             const float* __restrict__ W_v,  const float* __restrict__ b_v,
                             const float* __restrict__ W_o,  const float* __restrict__ b_o) {
    __shared__ float A[32][3], Bm[32][3], Cm[32][3];
    __shared__ float aQ[32], bK[32], cV[32];
    int tid = threadIdx.x;  // 128 threads

    for (int task = tid; task < 384; task += 128) {
        int m = task >> 7;
        int r = task & 127;
        const float* Wm = (m == 0) ? W_q : (m == 1) ? W_k : W_v;
        const float* bm = (m == 0) ? b_q : (m == 1) ? b_k : b_v;
        if (r < 96) {
            int o = r / 3, i = r - 3 * o;
            float s = 0.f;
            #pragma unroll
            for (int j = 0; j < 32; j++) s += Wm[o * 32 + j] * W_in[j * 3 + i];
            if (m == 0) A[o][i] = s; else if (m == 1) Bm[o][i] = s; else Cm[o][i] = s;
        } else {
            int o = r - 96;
            float s = bm[o];
            #pragma unroll
            for (int j = 0; j < 32; j++) s += Wm[o * 32 + j] * b_in[j];
            if (m == 0) aQ[o] = s; else if (m == 1) bK[o] = s; else cV[o] = s;
        }
    }
    __syncthreads();

    // 1/sqrt(8) * log2(e): fold softmax scale AND base-2 conversion into scores
    const float scale = 0.3535533905932738f * 1.4426950408889634f;
    if (tid < 103) {
        float s = 0.f;
        if (tid >= 100) {
            int o = tid - 100;
            s = b_o[o];
            #pragma unroll
            for (int r = 0; r < 32; r++) s += W_o[o * 32 + r] * cV[r];
        } else {
            int n = tid / 25, k = tid - 25 * n;
            int base = n * 8;
            if (k < 9) {
                int j = k / 3, i = k - 3 * j;
                #pragma unroll
                for (int d = 0; d < 8; d++) s += A[base + d][i] * Bm[base + d][j];
                s *= scale;
            } else if (k < 12) {
                int j = k - 9;
                #pragma unroll
                for (int d = 0; d < 8; d++) s += aQ[base + d] * Bm[base + d][j];
                s *= scale;
            } else if (k < 15) {
                int i = k - 12;
                #pragma unroll
                for (int d = 0; d < 8; d++) s += A[base + d][i] * bK[base + d];
                s *= scale;
            } else if (k == 15) {
                #pragma unroll
                for (int d = 0; d < 8; d++) s += aQ[base + d] * bK[base + d];
                s *= scale;
            } else {
                int kk = k - 16;
                int o = kk / 3, i = kk - 3 * o;
                #pragma unroll
                for (int d = 0; d < 8; d++) s += W_o[o * 32 + base + d] * Cm[base + d][i];
            }
        }
        g_const[tid] = s;
    }
}

// ---------------- main kernel: 2 pixels per thread, packed f32x2 ----------------
__global__ void __launch_bounds__(128)
attn_kernel(const float* __restrict__ z, float* __restrict__ out) {
    __shared__ f32x2 cst[103];
    int tid = threadIdx.x;
    if (tid < 103) { float c = g_const[tid]; cst[tid] = pack2(c, c); }
    __syncthreads();

    int gid = blockIdx.x * 128 + tid;       // 131072 threads total
    int pix = gid << 1;                     // 2 consecutive pixels
    int b  = pix >> 16;
    int hw = pix & (HW - 1);

    const float* zp = z + (size_t)b * (T_DIM * C_DIM * HW) + hw;
    f32x2 zv[24];                           // [t*3 + c], each holds 2 pixels
    #pragma unroll
    for (int i = 0; i < 24; i++)
        zv[i] = *reinterpret_cast<const f32x2*>(zp + (size_t)i * HW);

    f32x2 z70 = zv[21], z71 = zv[22], z72 = zv[23];
    f32x2 o0 = cst[100], o1 = cst[101], o2 = cst[102];

    #pragma unroll
    for (int n = 0; n < 4; n++) {
        const f32x2* cs = cst + n * 25;
        f32x2 r0 = fma2(cs[0], z70, fma2(cs[1], z71, fma2(cs[2], z72, cs[9])));
        f32x2 r1 = fma2(cs[3], z70, fma2(cs[4], z71, fma2(cs[5], z72, cs[10])));
        f32x2 r2 = fma2(cs[6], z70, fma2(cs[7], z71, fma2(cs[8], z72, cs[11])));
        f32x2 s  = fma2(cs[12], z70, fma2(cs[13], z71, fma2(cs[14], z72, cs[15])));

        f32x2 esum = 0ULL, zb0 = 0ULL, zb1 = 0ULL, zb2 = 0ULL;
        #pragma unroll
        for (int t = 0; t < T_DIM; t++) {
            f32x2 a0 = zv[t * 3], a1 = zv[t * 3 + 1], a2 = zv[t * 3 + 2];
            f32x2 sc = fma2(r0, a0, fma2(r1, a1, fma2(r2, a2, s)));
            f32x2 e  = ex2_2(sc);           // scores tiny (|sc|<~5): no max pass needed
            esum = add2(esum, e);
            zb0 = fma2(e, a0, zb0);
            zb1 = fma2(e, a1, zb1);
            zb2 = fma2(e, a2, zb2);
        }
        f32x2 inv = rcp_2(esum);
        zb0 = mul2(zb0, inv); zb1 = mul2(zb1, inv); zb2 = mul2(zb2, inv);
        o0 = fma2(cs[16], zb0, fma2(cs[17], zb1, fma2(cs[18], zb2, o0)));
        o1 = fma2(cs[19], zb0, fma2(cs[20], zb1, fma2(cs[21], zb2, o1)));
        o2 = fma2(cs[22], zb0, fma2(cs[23], zb1, fma2(cs[24], zb2, o2)));
    }

    float* op = out + (size_t)b * (3 * HW) + hw;
    *reinterpret_cast<f32x2*>(op)          = o0;
    *reinterpret_cast<f32x2*>(op + HW)     = o1;
    *reinterpret_cast<f32x2*>(op + 2 * HW) = o2;
}

extern "C" void kernel_launch(void* const* d_in, const int* in_sizes, int n_in,
                              void* d_out, int out_size) {
    const float* z    = (const float*)d_in[0];
    const float* W_in = (const float*)d_in[1];
    const float* b_in = (const float*)d_in[2];
    const float* W_q  = (const float*)d_in[3];
    const float* b_q  = (const float*)d_in[4];
    const float* W_k  = (const float*)d_in[5];
    const float* b_k  = (const float*)d_in[6];
    const float* W_v  = (const float*)d_in[7];
    const float* b_v  = (const float*)d_in[8];
    const float* W_o  = (const float*)d_in[9];
    const float* b_o  = (const float*)d_in[10];
    float* out = (float*)d_out;

    setup_kernel<<<1, 128>>>(W_in, b_in, W_q, b_q, W_k, b_k, W_v, b_v, W_o, b_o);
    attn_kernel<<<NPIX / 256, 128>>>(z, out);
}